// round 14
// baseline (speedup 1.0000x reference)
#include <cuda_runtime.h>
#include <cuda_bf16.h>

#define NUM_NODES   4000000
#define NUM_PHYS    3000000
#define HALF_PHYS   (NUM_PHYS / 2)
#define NUM_MOVABLE 2500000
#define HALF_MOV    (NUM_MOVABLE / 2)
#define NB          1024
#define NBINS       (NB * NB)

// 4 MB density map + 8 pad floats (vector windows may graze past map end with
// zero weights; harmless, never read).
__device__ float g_pmap[NBINS + 8];

__global__ __launch_bounds__(256) void zero_pmap_kernel() {
    int i = blockIdx.x * blockDim.x + threadIdx.x;
    reinterpret_cast<float4*>(g_pmap)[i] = make_float4(0.f, 0.f, 0.f, 0.f);
}

__device__ __forceinline__ void red_v2(float* p, float a, float b) {
    asm volatile("red.global.v2.f32.add [%0], {%1, %2};"
                 :: "l"(p), "f"(a), "f"(b) : "memory");
}
__device__ __forceinline__ void red_v4(float* p, float a, float b, float c, float d) {
    asm volatile("red.global.v4.f32.add [%0], {%1, %2, %3, %4};"
                 :: "l"(p), "f"(a), "f"(b), "f"(c), "f"(d) : "memory");
}

// ---------------------------------------------------------------------------
// Scatter (exact R13 win): live y-bins ⊆ {byl..byl+2}; single v4 RED when the
// trio fits a 16B quad (byl&3 <= 1), else two v2 REDs. 3-row x-loop,
// 2 nodes per thread.
// ---------------------------------------------------------------------------
__device__ __forceinline__ void scatter_one(
    const float* __restrict__ pos,
    const float* __restrict__ nsx,
    const float* __restrict__ nsy,
    const int*   __restrict__ pw,
    int i)
{
    float sx = nsx[i];
    float sy = nsy[i];
    float hx = 0.5f * fmaxf(1.414f, sx);   // bsx = bsy = 1.0
    float hy = 0.5f * fmaxf(1.414f, sy);
    float cx = pos[i]             + 0.5f * sx;
    float cy = pos[NUM_NODES + i] + 0.5f * sy;
    float xmin = cx - hx, xmax = cx + hx;
    float ymin = cy - hy, ymax = cy + hy;
    float dens = (float)pw[i] / (4.0f * hx * hy);

    int bxl = min(max((int)floorf(xmin), 0), NB - 1);
    int byl = min(max((int)floorf(ymin), 0), NB - 1);

    float w0, w1, w2;
    {
        float b0 = (float)byl;
        w0 = fmaxf(fminf(ymax, b0 + 1.0f) - fmaxf(ymin, b0), 0.0f);
        w1 = fmaxf(fminf(ymax, b0 + 2.0f) - fmaxf(ymin, b0 + 1.0f), 0.0f);
        w2 = fmaxf(fminf(ymax, b0 + 3.0f) - fmaxf(ymin, b0 + 2.0f), 0.0f);
    }

    int  m     = byl & 3;
    bool useq  = (m <= 1);
    int  base4 = byl & ~3;
    int  base2 = byl & ~1;

#pragma unroll
    for (int di = 0; di < 3; di++) {       // width <= 2.0 -> at most 3 rows
        int bx = bxl + di;
        if (bx >= NB) break;
        float bxf = (float)bx;
        float ox = fmaxf(fminf(xmax, bxf + 1.0f) - fmaxf(xmin, bxf), 0.0f);
        if (ox <= 0.0f) continue;
        float dox = dens * ox;
        float v0 = dox * w0, v1 = dox * w1, v2 = dox * w2;
        float* rowbase = g_pmap + bx * NB;
        if (useq) {
            if (m == 0) red_v4(rowbase + base4, v0, v1, v2, 0.0f);
            else        red_v4(rowbase + base4, 0.0f, v0, v1, v2);
        } else {
            if (m == 2) {
                red_v2(rowbase + base2, v0, v1);
                if (v2 != 0.0f) red_v2(rowbase + base2 + 2, v2, 0.0f);
            } else {
                red_v2(rowbase + base2, 0.0f, v0);
                if (v1 != 0.0f || v2 != 0.0f)
                    red_v2(rowbase + base2 + 2, v1, v2);
            }
        }
    }
}

__global__ __launch_bounds__(256) void scatter_kernel(
    const float* __restrict__ pos,
    const float* __restrict__ nsx,
    const float* __restrict__ nsy,
    const int*   __restrict__ pw)
{
    int i = blockIdx.x * blockDim.x + threadIdx.x;
    if (i >= HALF_PHYS) return;
    scatter_one(pos, nsx, nsy, pw, i);
    scatter_one(pos, nsx, nsy, pw, i + HALF_PHYS);
}

// ---------------------------------------------------------------------------
// Gather: v4/v2 hybrid mirroring scatter. byl&3 <= 1: single aligned float4
// covers the live trio (1 instr, 1 sector; dead slots weight 0). Else the
// R12 live-only pair/scalar mix. 3-row x-loop, 2 nodes/thread.
// ---------------------------------------------------------------------------
__device__ __forceinline__ float clip_adj(float p) {
    // adj = clip(pmap * 0.5, 0.4, 2.5); bsx*bsy == 1
    return fminf(fmaxf(p * 0.5f, 0.4f), 2.5f);
}

__device__ __forceinline__ float gather_one(
    const float* __restrict__ pos,
    const float* __restrict__ nsx,
    const float* __restrict__ nsy,
    int i)
{
    float mx  = pos[i];
    float my  = pos[NUM_NODES + i];
    float msx = nsx[i];
    float msy = nsy[i];
    float xmax = mx + msx;
    float ymax = my + msy;

    int bxl = min(max((int)floorf(mx), 0), NB - 1);
    int byl = min(max((int)floorf(my), 0), NB - 1);

    float o0, o1, o2;
    {
        float b0 = (float)byl;
        o0 = fmaxf(fminf(ymax, b0 + 1.0f) - fmaxf(my, b0), 0.0f);
        o1 = fmaxf(fminf(ymax, b0 + 2.0f) - fmaxf(my, b0 + 1.0f), 0.0f);
        o2 = fmaxf(fminf(ymax, b0 + 3.0f) - fmaxf(my, b0 + 2.0f), 0.0f);
    }

    int  m     = byl & 3;
    bool useq  = (m <= 1);
    int  base4 = byl & ~3;

    // quad slot weights (dead slots exactly 0)
    float q0, q1, q2, q3;
    if (m == 0) { q0 = o0; q1 = o1; q2 = o2; q3 = 0.0f; }
    else        { q0 = 0.0f; q1 = o0; q2 = o1; q3 = o2; }

    float area = 0.0f;
#pragma unroll
    for (int di = 0; di < 3; di++) {       // msx <= 2.0 -> at most 3 rows
        int bx = bxl + di;
        if (bx >= NB) break;
        float bxf = (float)bx;
        float ox = fmaxf(fminf(xmax, bxf + 1.0f) - fmaxf(mx, bxf), 0.0f);
        if (ox <= 0.0f) continue;
        const float* row = g_pmap + bx * NB;
        float s;
        if (useq) {
            float4 q = *reinterpret_cast<const float4*>(row + base4);
            s  = q0 * clip_adj(q.x) + q1 * clip_adj(q.y);
            s += q2 * clip_adj(q.z) + q3 * clip_adj(q.w);
        } else if (m == 2) {
            float2 p = *reinterpret_cast<const float2*>(row + byl);
            s = o0 * clip_adj(p.x) + o1 * clip_adj(p.y);
            if (o2 != 0.0f)
                s += o2 * clip_adj(row[byl + 2]);
        } else {   // m == 3
            s = o0 * clip_adj(row[byl]);
            if (o1 + o2 != 0.0f) {
                float2 p = *reinterpret_cast<const float2*>(row + byl + 1);
                s += o1 * clip_adj(p.x) + o2 * clip_adj(p.y);
            }
        }
        area = fmaf(ox, s, area);
    }
    return area;
}

__global__ __launch_bounds__(256) void gather_kernel(
    const float* __restrict__ pos,
    const float* __restrict__ nsx,
    const float* __restrict__ nsy,
    float*       __restrict__ out)
{
    int i = blockIdx.x * blockDim.x + threadIdx.x;
    if (i >= HALF_MOV) return;
    out[i]            = gather_one(pos, nsx, nsy, i);
    out[i + HALF_MOV] = gather_one(pos, nsx, nsy, i + HALF_MOV);
}

extern "C" void kernel_launch(void* const* d_in, const int* in_sizes, int n_in,
                              void* d_out, int out_size)
{
    const float* pos = (const float*)d_in[0];
    const float* nsx = (const float*)d_in[1];
    const float* nsy = (const float*)d_in[2];
    const int*   pw  = (const int*)  d_in[3];
    float* out = (float*)d_out;

    zero_pmap_kernel<<<(NBINS + 8) / 4 / 256, 256>>>();
    scatter_kernel<<<(HALF_PHYS + 255) / 256, 256>>>(pos, nsx, nsy, pw);
    gather_kernel<<<(HALF_MOV + 255) / 256, 256>>>(pos, nsx, nsy, out);
}

// round 15
// speedup vs baseline: 1.0948x; 1.0948x over previous
#include <cuda_runtime.h>
#include <cuda_bf16.h>

#define NUM_NODES   4000000
#define NUM_PHYS    3000000
#define HALF_PHYS   (NUM_PHYS / 2)
#define NUM_MOVABLE 2500000
#define HALF_MOV    (NUM_MOVABLE / 2)
#define NB          1024
#define NBINS       (NB * NB)

// 4 MB density map + 8 pad floats (vector windows may graze past map end with
// zero weights; harmless, never read).
__device__ float g_pmap[NBINS + 8];

__global__ __launch_bounds__(256) void zero_pmap_kernel() {
    int i = blockIdx.x * blockDim.x + threadIdx.x;
    reinterpret_cast<float4*>(g_pmap)[i] = make_float4(0.f, 0.f, 0.f, 0.f);
}

__device__ __forceinline__ void red_v2(float* p, float a, float b) {
    asm volatile("red.global.v2.f32.add [%0], {%1, %2};"
                 :: "l"(p), "f"(a), "f"(b) : "memory");
}
__device__ __forceinline__ void red_v4(float* p, float a, float b, float c, float d) {
    asm volatile("red.global.v4.f32.add [%0], {%1, %2, %3, %4};"
                 :: "l"(p), "f"(a), "f"(b), "f"(c), "f"(d) : "memory");
}

// ---------------------------------------------------------------------------
// Scatter (R13 win, x-bounds break removed): live y-bins ⊆ {byl..byl+2};
// single v4 RED when the trio fits a 16B quad (byl&3 <= 1), else two v2 REDs.
// xmax < 1024 strictly, so bx >= NB implies ox <= 0 -> continue guards all
// dereferences; no explicit bounds branch needed. 2 nodes per thread.
// ---------------------------------------------------------------------------
__device__ __forceinline__ void scatter_one(
    const float* __restrict__ pos,
    const float* __restrict__ nsx,
    const float* __restrict__ nsy,
    const int*   __restrict__ pw,
    int i)
{
    float sx = nsx[i];
    float sy = nsy[i];
    float hx = 0.5f * fmaxf(1.414f, sx);   // bsx = bsy = 1.0
    float hy = 0.5f * fmaxf(1.414f, sy);
    float cx = pos[i]             + 0.5f * sx;
    float cy = pos[NUM_NODES + i] + 0.5f * sy;
    float xmin = cx - hx, xmax = cx + hx;
    float ymin = cy - hy, ymax = cy + hy;
    float dens = (float)pw[i] / (4.0f * hx * hy);

    int bxl = min(max((int)floorf(xmin), 0), NB - 1);
    int byl = min(max((int)floorf(ymin), 0), NB - 1);

    float w0, w1, w2;
    {
        float b0 = (float)byl;
        w0 = fmaxf(fminf(ymax, b0 + 1.0f) - fmaxf(ymin, b0), 0.0f);
        w1 = fmaxf(fminf(ymax, b0 + 2.0f) - fmaxf(ymin, b0 + 1.0f), 0.0f);
        w2 = fmaxf(fminf(ymax, b0 + 3.0f) - fmaxf(ymin, b0 + 2.0f), 0.0f);
    }

    int  m     = byl & 3;
    bool useq  = (m <= 1);
    int  base4 = byl & ~3;
    int  base2 = byl & ~1;

#pragma unroll
    for (int di = 0; di < 3; di++) {       // width <= 2.0 -> at most 3 rows
        int bx = bxl + di;
        float bxf = (float)bx;
        float ox = fmaxf(fminf(xmax, bxf + 1.0f) - fmaxf(xmin, bxf), 0.0f);
        if (ox <= 0.0f) continue;          // also guards bx >= NB
        float dox = dens * ox;
        float v0 = dox * w0, v1 = dox * w1, v2 = dox * w2;
        float* rowbase = g_pmap + bx * NB;
        if (useq) {
            if (m == 0) red_v4(rowbase + base4, v0, v1, v2, 0.0f);
            else        red_v4(rowbase + base4, 0.0f, v0, v1, v2);
        } else {
            if (m == 2) {
                red_v2(rowbase + base2, v0, v1);
                if (v2 != 0.0f) red_v2(rowbase + base2 + 2, v2, 0.0f);
            } else {
                red_v2(rowbase + base2, 0.0f, v0);
                if (v1 != 0.0f || v2 != 0.0f)
                    red_v2(rowbase + base2 + 2, v1, v2);
            }
        }
    }
}

__global__ __launch_bounds__(256) void scatter_kernel(
    const float* __restrict__ pos,
    const float* __restrict__ nsx,
    const float* __restrict__ nsy,
    const int*   __restrict__ pw)
{
    int i = blockIdx.x * blockDim.x + threadIdx.x;
    if (i >= HALF_PHYS) return;
    scatter_one(pos, nsx, nsy, pw, i);
    scatter_one(pos, nsx, nsy, pw, i + HALF_PHYS);
}

// ---------------------------------------------------------------------------
// Gather (R13 win, x-bounds break removed): live-only hybrid loads, two-path
// even/odd split. 2 nodes/thread.
// ---------------------------------------------------------------------------
__device__ __forceinline__ float clip_adj(float p) {
    // adj = clip(pmap * 0.5, 0.4, 2.5); bsx*bsy == 1
    return fminf(fmaxf(p * 0.5f, 0.4f), 2.5f);
}

__device__ __forceinline__ float gather_one(
    const float* __restrict__ pos,
    const float* __restrict__ nsx,
    const float* __restrict__ nsy,
    int i)
{
    float mx  = pos[i];
    float my  = pos[NUM_NODES + i];
    float msx = nsx[i];
    float msy = nsy[i];
    float xmax = mx + msx;
    float ymax = my + msy;

    int bxl = min(max((int)floorf(mx), 0), NB - 1);
    int byl = min(max((int)floorf(my), 0), NB - 1);

    float o0, o1, o2;
    {
        float b0 = (float)byl;
        o0 = fmaxf(fminf(ymax, b0 + 1.0f) - fmaxf(my, b0), 0.0f);
        o1 = fmaxf(fminf(ymax, b0 + 2.0f) - fmaxf(my, b0 + 1.0f), 0.0f);
        o2 = fmaxf(fminf(ymax, b0 + 3.0f) - fmaxf(my, b0 + 2.0f), 0.0f);
    }
    bool odd = (byl & 1);

    float area = 0.0f;
#pragma unroll
    for (int di = 0; di < 3; di++) {       // msx <= 2.0 -> at most 3 rows
        int bx = bxl + di;
        float bxf = (float)bx;
        float ox = fmaxf(fminf(xmax, bxf + 1.0f) - fmaxf(mx, bxf), 0.0f);
        if (ox <= 0.0f) continue;          // also guards bx >= NB
        const float* row = g_pmap + bx * NB;
        float s;
        if (odd) {
            s = o0 * clip_adj(row[byl]);
            if (o1 + o2 != 0.0f) {
                float2 p = *reinterpret_cast<const float2*>(row + byl + 1);
                s += o1 * clip_adj(p.x) + o2 * clip_adj(p.y);
            }
        } else {
            float2 p = *reinterpret_cast<const float2*>(row + byl);
            s = o0 * clip_adj(p.x) + o1 * clip_adj(p.y);
            if (o2 != 0.0f)
                s += o2 * clip_adj(row[byl + 2]);
        }
        area = fmaf(ox, s, area);
    }
    return area;
}

__global__ __launch_bounds__(256) void gather_kernel(
    const float* __restrict__ pos,
    const float* __restrict__ nsx,
    const float* __restrict__ nsy,
    float*       __restrict__ out)
{
    int i = blockIdx.x * blockDim.x + threadIdx.x;
    if (i >= HALF_MOV) return;
    out[i]            = gather_one(pos, nsx, nsy, i);
    out[i + HALF_MOV] = gather_one(pos, nsx, nsy, i + HALF_MOV);
}

extern "C" void kernel_launch(void* const* d_in, const int* in_sizes, int n_in,
                              void* d_out, int out_size)
{
    const float* pos = (const float*)d_in[0];
    const float* nsx = (const float*)d_in[1];
    const float* nsy = (const float*)d_in[2];
    const int*   pw  = (const int*)  d_in[3];
    float* out = (float*)d_out;

    zero_pmap_kernel<<<(NBINS + 8) / 4 / 256, 256>>>();
    scatter_kernel<<<(HALF_PHYS + 255) / 256, 256>>>(pos, nsx, nsy, pw);
    gather_kernel<<<(HALF_MOV + 255) / 256, 256>>>(pos, nsx, nsy, out);
}

// round 16
// speedup vs baseline: 1.1242x; 1.0269x over previous
#include <cuda_runtime.h>
#include <cuda_bf16.h>

#define NUM_NODES   4000000
#define NUM_PHYS    3000000
#define HALF_PHYS   (NUM_PHYS / 2)
#define NUM_MOVABLE 2500000
#define HALF_MOV    (NUM_MOVABLE / 2)
#define NB          1024
#define NBINS       (NB * NB)

// 4 MB density map + 8 pad floats (vector windows may graze past map end with
// zero weights; harmless, never read).
__device__ float g_pmap[NBINS + 8];

__global__ __launch_bounds__(256) void zero_pmap_kernel() {
    int i = blockIdx.x * blockDim.x + threadIdx.x;
    reinterpret_cast<float4*>(g_pmap)[i] = make_float4(0.f, 0.f, 0.f, 0.f);
}

__device__ __forceinline__ void red_v2(float* p, float a, float b) {
    asm volatile("red.global.v2.f32.add [%0], {%1, %2};"
                 :: "l"(p), "f"(a), "f"(b) : "memory");
}
__device__ __forceinline__ void red_v4(float* p, float a, float b, float c, float d) {
    asm volatile("red.global.v4.f32.add [%0], {%1, %2, %3, %4};"
                 :: "l"(p), "f"(a), "f"(b), "f"(c), "f"(d) : "memory");
}

// ---------------------------------------------------------------------------
// Scatter map-access core (exact R13/R15 win): live y-bins ⊆ {byl..byl+2};
// single v4 RED when the trio fits a 16B quad (byl&3 <= 1), else two v2 REDs.
// ---------------------------------------------------------------------------
__device__ __forceinline__ void scatter_core(
    float px, float py, float sx, float sy, int w)
{
    float hx = 0.5f * fmaxf(1.414f, sx);   // bsx = bsy = 1.0
    float hy = 0.5f * fmaxf(1.414f, sy);
    float cx = px + 0.5f * sx;
    float cy = py + 0.5f * sy;
    float xmin = cx - hx, xmax = cx + hx;
    float ymin = cy - hy, ymax = cy + hy;
    float dens = (float)w / (4.0f * hx * hy);

    int bxl = min(max((int)floorf(xmin), 0), NB - 1);
    int byl = min(max((int)floorf(ymin), 0), NB - 1);

    float w0, w1, w2;
    {
        float b0 = (float)byl;
        w0 = fmaxf(fminf(ymax, b0 + 1.0f) - fmaxf(ymin, b0), 0.0f);
        w1 = fmaxf(fminf(ymax, b0 + 2.0f) - fmaxf(ymin, b0 + 1.0f), 0.0f);
        w2 = fmaxf(fminf(ymax, b0 + 3.0f) - fmaxf(ymin, b0 + 2.0f), 0.0f);
    }

    int  m     = byl & 3;
    bool useq  = (m <= 1);
    int  base4 = byl & ~3;
    int  base2 = byl & ~1;

#pragma unroll
    for (int di = 0; di < 3; di++) {       // width <= 2.0 -> at most 3 rows
        int bx = bxl + di;
        float bxf = (float)bx;
        float ox = fmaxf(fminf(xmax, bxf + 1.0f) - fmaxf(xmin, bxf), 0.0f);
        if (ox <= 0.0f) continue;          // also guards bx >= NB
        float dox = dens * ox;
        float v0 = dox * w0, v1 = dox * w1, v2 = dox * w2;
        float* rowbase = g_pmap + bx * NB;
        if (useq) {
            if (m == 0) red_v4(rowbase + base4, v0, v1, v2, 0.0f);
            else        red_v4(rowbase + base4, 0.0f, v0, v1, v2);
        } else {
            if (m == 2) {
                red_v2(rowbase + base2, v0, v1);
                if (v2 != 0.0f) red_v2(rowbase + base2 + 2, v2, 0.0f);
            } else {
                red_v2(rowbase + base2, 0.0f, v0);
                if (v1 != 0.0f || v2 != 0.0f)
                    red_v2(rowbase + base2 + 2, v1, v2);
            }
        }
    }
}

// Adjacent-pair driver: vectorized float2/int2 input loads, two independent
// map-access streams per thread.
__global__ __launch_bounds__(256) void scatter_kernel(
    const float* __restrict__ pos,
    const float* __restrict__ nsx,
    const float* __restrict__ nsy,
    const int*   __restrict__ pw)
{
    int t = blockIdx.x * blockDim.x + threadIdx.x;
    if (t >= HALF_PHYS) return;
    int i = 2 * t;

    float2 px = *reinterpret_cast<const float2*>(pos + i);
    float2 py = *reinterpret_cast<const float2*>(pos + NUM_NODES + i);
    float2 sx = *reinterpret_cast<const float2*>(nsx + i);
    float2 sy = *reinterpret_cast<const float2*>(nsy + i);
    int2   w  = *reinterpret_cast<const int2*>(pw + i);

    scatter_core(px.x, py.x, sx.x, sy.x, w.x);
    scatter_core(px.y, py.y, sx.y, sy.y, w.y);
}

// ---------------------------------------------------------------------------
// Gather map-access core (exact R13/R15 win): live-only hybrid loads,
// two-path even/odd split.
// ---------------------------------------------------------------------------
__device__ __forceinline__ float clip_adj(float p) {
    // adj = clip(pmap * 0.5, 0.4, 2.5); bsx*bsy == 1
    return fminf(fmaxf(p * 0.5f, 0.4f), 2.5f);
}

__device__ __forceinline__ float gather_core(
    float mx, float my, float msx, float msy)
{
    float xmax = mx + msx;
    float ymax = my + msy;

    int bxl = min(max((int)floorf(mx), 0), NB - 1);
    int byl = min(max((int)floorf(my), 0), NB - 1);

    float o0, o1, o2;
    {
        float b0 = (float)byl;
        o0 = fmaxf(fminf(ymax, b0 + 1.0f) - fmaxf(my, b0), 0.0f);
        o1 = fmaxf(fminf(ymax, b0 + 2.0f) - fmaxf(my, b0 + 1.0f), 0.0f);
        o2 = fmaxf(fminf(ymax, b0 + 3.0f) - fmaxf(my, b0 + 2.0f), 0.0f);
    }
    bool odd = (byl & 1);

    float area = 0.0f;
#pragma unroll
    for (int di = 0; di < 3; di++) {       // msx <= 2.0 -> at most 3 rows
        int bx = bxl + di;
        float bxf = (float)bx;
        float ox = fmaxf(fminf(xmax, bxf + 1.0f) - fmaxf(mx, bxf), 0.0f);
        if (ox <= 0.0f) continue;          // also guards bx >= NB
        const float* row = g_pmap + bx * NB;
        float s;
        if (odd) {
            s = o0 * clip_adj(row[byl]);
            if (o1 + o2 != 0.0f) {
                float2 p = *reinterpret_cast<const float2*>(row + byl + 1);
                s += o1 * clip_adj(p.x) + o2 * clip_adj(p.y);
            }
        } else {
            float2 p = *reinterpret_cast<const float2*>(row + byl);
            s = o0 * clip_adj(p.x) + o1 * clip_adj(p.y);
            if (o2 != 0.0f)
                s += o2 * clip_adj(row[byl + 2]);
        }
        area = fmaf(ox, s, area);
    }
    return area;
}

__global__ __launch_bounds__(256) void gather_kernel(
    const float* __restrict__ pos,
    const float* __restrict__ nsx,
    const float* __restrict__ nsy,
    float*       __restrict__ out)
{
    int t = blockIdx.x * blockDim.x + threadIdx.x;
    if (t >= HALF_MOV) return;
    int i = 2 * t;

    float2 mx  = *reinterpret_cast<const float2*>(pos + i);
    float2 my  = *reinterpret_cast<const float2*>(pos + NUM_NODES + i);
    float2 msx = *reinterpret_cast<const float2*>(nsx + i);
    float2 msy = *reinterpret_cast<const float2*>(nsy + i);

    float2 r;
    r.x = gather_core(mx.x, my.x, msx.x, msy.x);
    r.y = gather_core(mx.y, my.y, msx.y, msy.y);
    *reinterpret_cast<float2*>(out + i) = r;
}

extern "C" void kernel_launch(void* const* d_in, const int* in_sizes, int n_in,
                              void* d_out, int out_size)
{
    const float* pos = (const float*)d_in[0];
    const float* nsx = (const float*)d_in[1];
    const float* nsy = (const float*)d_in[2];
    const int*   pw  = (const int*)  d_in[3];
    float* out = (float*)d_out;

    zero_pmap_kernel<<<(NBINS + 8) / 4 / 256, 256>>>();
    scatter_kernel<<<(HALF_PHYS + 255) / 256, 256>>>(pos, nsx, nsy, pw);
    gather_kernel<<<(HALF_MOV + 255) / 256, 256>>>(pos, nsx, nsy, out);
}